// round 16
// baseline (speedup 1.0000x reference)
#include <cuda_runtime.h>
#include <cuda_bf16.h>
#include <math.h>
#include <stdint.h>

#define TB 256
#define TT 200
#define TV 16
#define TN 64
#define TG 1024   // V*N
#define TK 1040   // V*(N+1)
#define NCTA 128
#define RTHREADS 256

__device__ float g_xT[TT][TV][TB];
__device__ float g_hsT[TT][TG][TB];
__device__ float g_aunT[TT][TV][TB];
__device__ float g_inv[TV][TB];
__device__ float g_gT[TG][TB];
__device__ __align__(16) uint32_t g_hA_hi[64 * 16 * 32 * 4];   // A fragments (h) bf16
__device__ __align__(16) uint32_t g_xA[TT][2048];              // A fragments (x) bf16, per step
__device__ __align__(16) uint32_t g_WB_hi[65 * 384 * 32 * 2];  // B fragments (W) bf16, kc 64 = x-part
__device__ unsigned g_bar;

__device__ __forceinline__ void mma_bf16(float* d, const uint32_t* a, const uint32_t* b) {
    asm volatile(
        "mma.sync.aligned.m16n8k16.row.col.f32.bf16.bf16.f32 "
        "{%0,%1,%2,%3}, {%4,%5,%6,%7}, {%8,%9}, {%0,%1,%2,%3};"
        : "+f"(d[0]), "+f"(d[1]), "+f"(d[2]), "+f"(d[3])
        : "r"(a[0]), "r"(a[1]), "r"(a[2]), "r"(a[3]), "r"(b[0]), "r"(b[1]));
}

__device__ __forceinline__ uint32_t pack_bf(float v0, float v1) {
    __nv_bfloat162 t = { __float2bfloat16(v0), __float2bfloat16(v1) };
    return *reinterpret_cast<uint32_t*>(&t);
}

__device__ __forceinline__ float fsigmoid(float z) {
    return __fdividef(1.f, 1.f + __expf(-z));
}
__device__ __forceinline__ float ftanh(float x) {
    float cx = fminf(fmaxf(x, -9.f), 9.f);
    float e = __expf(2.f * cx);
    return __fdividef(e - 1.f, e + 1.f);
}

__global__ void k_xT(const float* __restrict__ x) {
    int t = blockIdx.x >> 4, v = blockIdx.x & 15, b = threadIdx.x;
    g_xT[t][v][b] = x[(size_t)b * (TT * TV) + t * TV + v];
    if (blockIdx.x == 0 && threadIdx.x == 0) g_bar = 0u;
}

// x A-fragments for all steps
__global__ void k_xfrag(const float* __restrict__ x) {
    int t = blockIdx.x;
    for (int e = threadIdx.x; e < 2048; e += 256) {
        int reg = e & 3, lane = (e >> 2) & 31, mt = e >> 7;
        int m = mt * 16 + (lane >> 2) + 8 * (reg & 1);
        int k0 = (lane & 3) * 2 + (reg >> 1) * 8;
        g_xA[t][e] = pack_bf(x[(size_t)m * (TT * TV) + t * TV + k0],
                             x[(size_t)m * (TT * TV) + t * TV + k0 + 1]);
    }
}

// bf16 B fragments of gate weights: kc 0..63 = h-part (cols 16..1039), kc 64 = x-part (cols 0..15)
__global__ void k_wfrag(const float* __restrict__ Wi, const float* __restrict__ Wf,
                        const float* __restrict__ Wo) {
    int nt = blockIdx.x, kc = blockIdx.y;
    int l = threadIdx.x & 31, reg = threadIdx.x >> 5;
    int n = nt * 8 + (l >> 2);
    int gate = n >> 10, u = n & 1023;
    const float* W = (gate == 0) ? Wi : (gate == 1) ? Wf : Wo;
    int kk = (l & 3) * 2 + reg * 8;
    int col = (kc == 64) ? kk : (16 + kc * 16 + kk);
    float v0 = W[(size_t)u * TK + col];
    float v1 = W[(size_t)u * TK + col + 1];
    g_WB_hi[((size_t)(kc * 384 + nt) * 32 + l) * 2 + reg] = pack_bf(v0, v1);
}

__global__ void __launch_bounds__(RTHREADS, 1) k_recur(
    const float* __restrict__ U_j, const float* __restrict__ W_j, const float* __restrict__ b_j,
    const float* __restrict__ bi, const float* __restrict__ bf_, const float* __restrict__ bo)
{
    __shared__ float s_bg[48];
    __shared__ float s_bj[16];
    __shared__ float s_uu[16];
    extern __shared__ uint32_t smdyn[];
    uint32_t* s_Bh = smdyn;                     // [6 gj][65 kc][32 l][2 reg] = 24960 u32
    uint32_t* s_Bj = smdyn + 24960;             // [2 jt][4 kk][32 l][2 reg] = 512 u32
    float*    s_D  = (float*)(smdyn + 25472);   // [64 n][128 m] (rows 48..63 = j)

    const int tid = threadIdx.x, cta = blockIdx.x;
    const int lane = tid & 31, wid = tid >> 5;
    const int mh = cta & 1, ng = cta >> 1;
    const int g0 = ng * 16, v = g0 >> 6, n0 = g0 & 63;
    const int bl = tid & 127, uh = tid >> 7;
    const int bg = mh * 128 + bl;

    // ---- one-time staging ----
    if (tid < 48) {
        int g = tid >> 4, u = tid & 15;
        s_bg[tid] = ((g == 0) ? bi : (g == 1) ? bf_ : bo)[g0 + u];
    }
    if (tid < 16) { s_bj[tid] = b_j[v * TN + n0 + tid]; s_uu[tid] = U_j[v * TN + n0 + tid]; }
    // gate B fragments (65 kc): nt = g*128 + ng*2 + j
    for (int e = tid; e < 24960; e += RTHREADS) {
        int gj = e / 4160, r = e - gj * 4160;
        int kc = r >> 6, l = (r >> 1) & 31, reg = e & 1;
        int g = gj >> 1, j = gj & 1;
        s_Bh[e] = g_WB_hi[((size_t)(kc * 384 + g * 128 + ng * 2 + j) * 32 + l) * 2 + reg];
    }
    // j B fragments: W_j^T
    for (int e = tid; e < 512; e += RTHREADS) {
        int reg = e & 1, l = (e >> 1) & 31, kk = (e >> 6) & 3, jt = e >> 8;
        int n = jt * 8 + (l >> 2);
        int k0 = kk * 16 + (l & 3) * 2 + reg * 8;
        float v0 = W_j[v * TN * TN + k0 * TN + (n0 + n)];
        float v1 = W_j[v * TN * TN + (k0 + 1) * TN + (n0 + n)];
        s_Bj[e] = pack_bf(v0, v1);
    }
    __syncthreads();

    // epilogue A-fragment write constants
    const int mt_e = bg >> 4, r_e = bg & 15;
    const int reg_e = ((r_e >> 3) & 1) | (uh << 1);
    const int lane_e = (r_e & 7) * 4;

    float cc[8];
    #pragma unroll
    for (int u = 0; u < 8; ++u) cc[u] = 0.f;

    for (int t = 0; t < TT; ++t) {
        // ========== GEMM: M=128 x (48 gate + 16 j), K = 16 x + (t>0 ? 1024 h : 0) ==========
        {
            float acc[6][4];
            #pragma unroll
            for (int gj = 0; gj < 6; ++gj)
                #pragma unroll
                for (int q = 0; q < 4; ++q) acc[gj][q] = 0.f;

            const uint4* __restrict__ Ah = (const uint4*)g_hA_hi;
            const uint4* __restrict__ Ax = (const uint4*)g_xA;
            const int mt = mh * 8 + wid;

            // x part (kc = 64), always
            {
                uint4 ax = Ax[(size_t)t * 512 + mt * 32 + lane];
                #pragma unroll
                for (int gj = 0; gj < 6; ++gj) {
                    uint2 bh = *(const uint2*)&s_Bh[(gj * 65 + 64) * 64 + lane * 2];
                    mma_bf16(acc[gj], (const uint32_t*)&ax, (const uint32_t*)&bh);
                }
            }
            if (t > 0) {
                // h part, depth-2 prefetch
                uint4 aa = Ah[(0 * 16 + mt) * 32 + lane];
                uint4 ab = Ah[(1 * 16 + mt) * 32 + lane];
                #pragma unroll 2
                for (int kc = 0; kc < 64; ++kc) {
                    uint4 nh;
                    if (kc + 2 < 64) nh = Ah[((kc + 2) * 16 + mt) * 32 + lane];
                    #pragma unroll
                    for (int gj = 0; gj < 6; ++gj) {
                        uint2 bh = *(const uint2*)&s_Bh[(gj * 65 + kc) * 64 + lane * 2];
                        mma_bf16(acc[gj], (const uint32_t*)&aa, (const uint32_t*)&bh);
                    }
                    aa = ab;
                    if (kc + 2 < 64) ab = nh;
                }
                // block-diagonal j
                float accj[2][4];
                #pragma unroll
                for (int jt = 0; jt < 2; ++jt)
                    #pragma unroll
                    for (int q = 0; q < 4; ++q) accj[jt][q] = 0.f;
                #pragma unroll
                for (int kk = 0; kk < 4; ++kk) {
                    uint4 aj = Ah[((v * 4 + kk) * 16 + mt) * 32 + lane];
                    #pragma unroll
                    for (int jt = 0; jt < 2; ++jt) {
                        uint2 bj = *(const uint2*)&s_Bj[((jt * 4 + kk) * 32 + lane) * 2];
                        mma_bf16(accj[jt], (const uint32_t*)&aj, (const uint32_t*)&bj);
                    }
                }
                int m = wid * 16 + (lane >> 2);
                #pragma unroll
                for (int jt = 0; jt < 2; ++jt) {
                    int n = 48 + jt * 8 + (lane & 3) * 2;
                    s_D[n * 128 + m]           = accj[jt][0];
                    s_D[(n + 1) * 128 + m]     = accj[jt][1];
                    s_D[n * 128 + m + 8]       = accj[jt][2];
                    s_D[(n + 1) * 128 + m + 8] = accj[jt][3];
                }
            }
            // gate transpose store (always)
            int m = wid * 16 + (lane >> 2);
            #pragma unroll
            for (int gj = 0; gj < 6; ++gj) {
                int n = (gj >> 1) * 16 + (gj & 1) * 8 + (lane & 3) * 2;
                s_D[n * 128 + m]           = acc[gj][0];
                s_D[(n + 1) * 128 + m]     = acc[gj][1];
                s_D[n * 128 + m + 8]       = acc[gj][2];
                s_D[(n + 1) * 128 + m + 8] = acc[gj][3];
            }
        }
        __syncthreads();

        // ========== epilogue (thread = batch bg, units g0+uh*8 .. +7) ==========
        {
            float xvo = g_xT[t][v][bg];
            float hval[8];
            float* ho = &g_hsT[t][0][0];
            #pragma unroll
            for (int ul = 0; ul < 8; ++ul) {
                int r = uh * 8 + ul;
                float zi = s_bg[r]      + s_D[r * 128 + bl];
                float zf = s_bg[16 + r] + s_D[(16 + r) * 128 + bl];
                float zo = s_bg[32 + r] + s_D[(32 + r) * 128 + bl];
                float jz = s_bj[r] + xvo * s_uu[r];
                if (t > 0) jz += s_D[(48 + r) * 128 + bl];
                float iv = fsigmoid(zi);
                float fv = fsigmoid(zf);
                float ov = fsigmoid(zo);
                float jv = ftanh(jz);
                float cn = cc[ul] * fv + iv * jv;
                cc[ul] = cn;
                hval[ul] = ov * ftanh(cn);
                ho[(size_t)(g0 + r) * TB + bg] = hval[ul];
            }
            #pragma unroll
            for (int p = 0; p < 4; ++p) {
                size_t idx = ((size_t)(ng * 16 + mt_e) * 32 + lane_e + p) * 4 + reg_e;
                g_hA_hi[idx] = pack_bf(hval[2 * p], hval[2 * p + 1]);
            }
        }

        // single grid barrier per step
        __syncthreads();
        if (tid == 0) {
            __threadfence(); atomicAdd(&g_bar, 1u);
            unsigned target = (unsigned)(t + 1) * NCTA;
            while (*((volatile unsigned*)&g_bar) < target) { }
            __threadfence();
        }
        __syncthreads();
    }
}

__global__ void k_alphaA(const float* __restrict__ Fa, const float* __restrict__ Fab) {
    __shared__ float fa[TN]; __shared__ float fabv;
    int v = blockIdx.x, t0 = blockIdx.y * 8, b = threadIdx.x;
    if (threadIdx.x < TN) fa[threadIdx.x] = Fa[v * TN + threadIdx.x];
    if (threadIdx.x == 0) fabv = Fab[v];
    __syncthreads();
    for (int t = t0; t < t0 + 8; ++t) {
        const float* hr = &g_hsT[t][v * TN][0];
        float ap = fabv;
        #pragma unroll 8
        for (int n = 0; n < TN; ++n) ap += hr[n * TB + b] * fa[n];
        g_aunT[t][v][b] = expf(tanhf(ap));
    }
}

__global__ void k_alphaInv() {
    int v = blockIdx.x, b = threadIdx.x;
    float s = 0.f;
    for (int t = 0; t < TT; ++t) s += g_aunT[t][v][b];
    g_inv[v][b] = 1.f / s;
}

__global__ void k_gn() {
    int v = blockIdx.x, nc = blockIdx.y * 2, b = threadIdx.x;
    float a0 = 0.f, a1 = 0.f;
    for (int t = 0; t < TT; ++t) {
        float au = g_aunT[t][v][b];
        const float* hr = &g_hsT[t][v * TN + nc][0];
        a0 += au * hr[0 * TB + b];
        a1 += au * hr[1 * TB + b];
    }
    float inv = g_inv[v][b];
    g_gT[v * TN + nc + 0][b] = a0 * inv;
    g_gT[v * TN + nc + 1][b] = a1 * inv;
}

__global__ void k_alphaOut(float* __restrict__ out) {
    int t = blockIdx.x, b = threadIdx.x;
    float* ao = out + TB;
    #pragma unroll
    for (int v = 0; v < TV; ++v)
        ao[((size_t)b * TT + t) * TV + v] = g_aunT[t][v][b] * g_inv[v][b];
}

__global__ void k_final(const float* __restrict__ Fbw, const float* __restrict__ Fbb,
                        const float* __restrict__ Phw, const float* __restrict__ Phb,
                        float* __restrict__ out) {
    __shared__ float phi[2 * TN], fbw[2 * TN];
    __shared__ float phib, fbb;
    int b = threadIdx.x;
    if (threadIdx.x < 2 * TN) { phi[threadIdx.x] = Phw[threadIdx.x]; fbw[threadIdx.x] = Fbw[threadIdx.x]; }
    if (threadIdx.x == 0) { phib = Phb[0]; fbb = Fbb[0]; }
    __syncthreads();
    float mu[TV], bu[TV], bs = 0.f;
    #pragma unroll
    for (int v = 0; v < TV; ++v) {
        const float* gr = &g_gT[v * TN][0];
        const float* hr = &g_hsT[TT - 1][v * TN][0];
        float m_ = phib, p_ = fbb;
        #pragma unroll 8
        for (int n = 0; n < TN; ++n) {
            float gv = gr[n * TB + b], hv = hr[n * TB + b];
            m_ += gv * phi[n] + hv * phi[TN + n];
            p_ += gv * fbw[n] + hv * fbw[TN + n];
        }
        mu[v] = m_;
        float e = expf(tanhf(p_));
        bu[v] = e; bs += e;
    }
    float ib = 1.f / bs, mean = 0.f;
    float* bout = out + TB + (size_t)TB * TT * TV;
    #pragma unroll
    for (int v = 0; v < TV; ++v) {
        float be = bu[v] * ib;
        mean += be * mu[v];
        bout[(size_t)b * TV + v] = be;
    }
    out[b] = mean;
}

extern "C" void kernel_launch(void* const* d_in, const int* in_sizes, int n_in,
                              void* d_out, int out_size) {
    const float* x    = (const float*)d_in[0];
    const float* U_j  = (const float*)d_in[1];
    const float* W_j  = (const float*)d_in[2];
    const float* b_j  = (const float*)d_in[3];
    const float* Wi   = (const float*)d_in[4];
    const float* bi   = (const float*)d_in[5];
    const float* Wf   = (const float*)d_in[6];
    const float* bf   = (const float*)d_in[7];
    const float* Wo   = (const float*)d_in[8];
    const float* bo   = (const float*)d_in[9];
    const float* Fa   = (const float*)d_in[10];
    const float* Fab  = (const float*)d_in[11];
    const float* Fbw  = (const float*)d_in[12];
    const float* Fbb  = (const float*)d_in[13];
    const float* Phw  = (const float*)d_in[14];
    const float* Phb  = (const float*)d_in[15];
    float* out = (float*)d_out;

    static const int SMEM = 24960 * 4 + 512 * 4 + 64 * 128 * 4;  // 134656 B
    cudaFuncSetAttribute(k_recur, cudaFuncAttributeMaxDynamicSharedMemorySize, SMEM);

    k_xT<<<TT * TV, TB>>>(x);
    k_xfrag<<<TT, 256>>>(x);
    k_wfrag<<<dim3(384, 65), 64>>>(Wi, Wf, Wo);
    k_recur<<<NCTA, RTHREADS, SMEM>>>(U_j, W_j, b_j, bi, bf, bo);
    k_alphaA<<<dim3(TV, 25), TB>>>(Fa, Fab);
    k_alphaInv<<<TV, TB>>>();
    k_gn<<<dim3(TV, 32), TB>>>();
    k_alphaOut<<<TT, TB>>>(out);
    k_final<<<1, TB>>>(Fbw, Fbb, Phw, Phb, out);
}

// round 17
// speedup vs baseline: 1.7294x; 1.7294x over previous
#include <cuda_runtime.h>
#include <cuda_bf16.h>
#include <math.h>
#include <stdint.h>

#define TB 256
#define TT 200
#define TV 16
#define TN 64
#define TG 1024   // V*N
#define TK 1040   // V*(N+1)
#define NCTA 128
#define RTHREADS 256

__device__ float g_xT[TT][TV][TB];
__device__ float g_hsT[TT][TG][TB];
__device__ float g_aunT[TT][TV][TB];
__device__ float g_inv[TV][TB];
__device__ float g_gT[TG][TB];
__device__ __align__(16) uint32_t g_hA_hi[64 * 16 * 32 * 4];   // A fragments (h) bf16
__device__ __align__(16) uint32_t g_xA[TT][2048];              // A fragments (x) bf16, per step
__device__ __align__(16) uint32_t g_WB_hi[65 * 384 * 32 * 2];  // B fragments (W) bf16, kc 64 = x-part
__device__ unsigned g_bar;

__device__ __forceinline__ void mma_bf16(float* d, const uint32_t* a, const uint32_t* b) {
    asm volatile(
        "mma.sync.aligned.m16n8k16.row.col.f32.bf16.bf16.f32 "
        "{%0,%1,%2,%3}, {%4,%5,%6,%7}, {%8,%9}, {%0,%1,%2,%3};"
        : "+f"(d[0]), "+f"(d[1]), "+f"(d[2]), "+f"(d[3])
        : "r"(a[0]), "r"(a[1]), "r"(a[2]), "r"(a[3]), "r"(b[0]), "r"(b[1]));
}

__device__ __forceinline__ uint32_t pack_bf(float v0, float v1) {
    __nv_bfloat162 t = { __float2bfloat16(v0), __float2bfloat16(v1) };
    return *reinterpret_cast<uint32_t*>(&t);
}

__device__ __forceinline__ float fsigmoid(float z) {
    return __fdividef(1.f, 1.f + __expf(-z));
}
__device__ __forceinline__ float ftanh(float x) {
    float cx = fminf(fmaxf(x, -9.f), 9.f);
    float e = __expf(2.f * cx);
    return __fdividef(e - 1.f, e + 1.f);
}

__global__ void k_xT(const float* __restrict__ x) {
    int t = blockIdx.x >> 4, v = blockIdx.x & 15, b = threadIdx.x;
    g_xT[t][v][b] = x[(size_t)b * (TT * TV) + t * TV + v];
    if (blockIdx.x == 0 && threadIdx.x == 0) g_bar = 0u;
}

// x A-fragments for all steps
__global__ void k_xfrag(const float* __restrict__ x) {
    int t = blockIdx.x;
    for (int e = threadIdx.x; e < 2048; e += 256) {
        int reg = e & 3, lane = (e >> 2) & 31, mt = e >> 7;
        int m = mt * 16 + (lane >> 2) + 8 * (reg & 1);
        int k0 = (lane & 3) * 2 + (reg >> 1) * 8;
        g_xA[t][e] = pack_bf(x[(size_t)m * (TT * TV) + t * TV + k0],
                             x[(size_t)m * (TT * TV) + t * TV + k0 + 1]);
    }
}

// bf16 B fragments of gate weights: kc 0..63 = h-part (cols 16..1039), kc 64 = x-part (cols 0..15)
__global__ void k_wfrag(const float* __restrict__ Wi, const float* __restrict__ Wf,
                        const float* __restrict__ Wo) {
    int nt = blockIdx.x, kc = blockIdx.y;
    int l = threadIdx.x & 31, reg = threadIdx.x >> 5;
    int n = nt * 8 + (l >> 2);
    int gate = n >> 10, u = n & 1023;
    const float* W = (gate == 0) ? Wi : (gate == 1) ? Wf : Wo;
    int kk = (l & 3) * 2 + reg * 8;
    int col = (kc == 64) ? kk : (16 + kc * 16 + kk);
    float v0 = W[(size_t)u * TK + col];
    float v1 = W[(size_t)u * TK + col + 1];
    g_WB_hi[((size_t)(kc * 384 + nt) * 32 + l) * 2 + reg] = pack_bf(v0, v1);
}

__global__ void __launch_bounds__(RTHREADS, 1) k_recur(
    const float* __restrict__ U_j, const float* __restrict__ W_j, const float* __restrict__ b_j,
    const float* __restrict__ bi, const float* __restrict__ bf_, const float* __restrict__ bo)
{
    __shared__ float s_bg[48];
    __shared__ float s_bj[16];
    __shared__ float s_uu[16];
    extern __shared__ uint32_t smdyn[];
    uint32_t* s_Bh = smdyn;                     // [6 gj][65 kc][32 l][2 reg] = 24960 u32
    uint32_t* s_Bj = smdyn + 24960;             // [2 jt][4 kk][32 l][2 reg] = 512 u32
    float*    s_D  = (float*)(smdyn + 25472);   // [64 n][128 m] (rows 48..63 = j)

    const int tid = threadIdx.x, cta = blockIdx.x;
    const int lane = tid & 31, wid = tid >> 5;
    const int mh = cta & 1, ng = cta >> 1;
    const int g0 = ng * 16, v = g0 >> 6, n0 = g0 & 63;
    const int bl = tid & 127, uh = tid >> 7;
    const int bg = mh * 128 + bl;

    // ---- one-time staging ----
    if (tid < 48) {
        int g = tid >> 4, u = tid & 15;
        s_bg[tid] = ((g == 0) ? bi : (g == 1) ? bf_ : bo)[g0 + u];
    }
    if (tid < 16) { s_bj[tid] = b_j[v * TN + n0 + tid]; s_uu[tid] = U_j[v * TN + n0 + tid]; }
    // gate B fragments (65 kc): nt = g*128 + ng*2 + j
    for (int e = tid; e < 24960; e += RTHREADS) {
        int gj = e / 4160, r = e - gj * 4160;
        int kc = r >> 6, l = (r >> 1) & 31, reg = e & 1;
        int g = gj >> 1, j = gj & 1;
        s_Bh[e] = g_WB_hi[((size_t)(kc * 384 + g * 128 + ng * 2 + j) * 32 + l) * 2 + reg];
    }
    // j B fragments: W_j^T
    for (int e = tid; e < 512; e += RTHREADS) {
        int reg = e & 1, l = (e >> 1) & 31, kk = (e >> 6) & 3, jt = e >> 8;
        int n = jt * 8 + (l >> 2);
        int k0 = kk * 16 + (l & 3) * 2 + reg * 8;
        float v0 = W_j[v * TN * TN + k0 * TN + (n0 + n)];
        float v1 = W_j[v * TN * TN + (k0 + 1) * TN + (n0 + n)];
        s_Bj[e] = pack_bf(v0, v1);
    }
    __syncthreads();

    // epilogue A-fragment write constants
    const int mt_e = bg >> 4, r_e = bg & 15;
    const int reg_e = ((r_e >> 3) & 1) | (uh << 1);
    const int lane_e = (r_e & 7) * 4;

    float cc[8];
    #pragma unroll
    for (int u = 0; u < 8; ++u) cc[u] = 0.f;

    for (int t = 0; t < TT; ++t) {
        // ========== GEMM: M=128 x (48 gate + 16 j), K = 16 x + (t>0 ? 1024 h : 0) ==========
        {
            float acc[6][4];
            #pragma unroll
            for (int gj = 0; gj < 6; ++gj)
                #pragma unroll
                for (int q = 0; q < 4; ++q) acc[gj][q] = 0.f;

            const uint4* __restrict__ Ah = (const uint4*)g_hA_hi;
            const uint4* __restrict__ Ax = (const uint4*)g_xA;
            const int mt = mh * 8 + wid;

            // x part (kc = 64), always
            {
                uint4 ax = Ax[(size_t)t * 512 + mt * 32 + lane];
                #pragma unroll
                for (int gj = 0; gj < 6; ++gj) {
                    uint2 bh = *(const uint2*)&s_Bh[(gj * 65 + 64) * 64 + lane * 2];
                    mma_bf16(acc[gj], (const uint32_t*)&ax, (const uint32_t*)&bh);
                }
            }
            if (t > 0) {
                // h part, depth-1 prefetch (R14-proven configuration)
                uint4 ah = Ah[(0 * 16 + mt) * 32 + lane];
                #pragma unroll 4
                for (int kc = 0; kc < 64; ++kc) {
                    uint4 nah;
                    if (kc < 63) nah = Ah[((kc + 1) * 16 + mt) * 32 + lane];
                    #pragma unroll
                    for (int gj = 0; gj < 6; ++gj) {
                        uint2 bh = *(const uint2*)&s_Bh[(gj * 65 + kc) * 64 + lane * 2];
                        mma_bf16(acc[gj], (const uint32_t*)&ah, (const uint32_t*)&bh);
                    }
                    if (kc < 63) ah = nah;
                }
                // block-diagonal j
                float accj[2][4];
                #pragma unroll
                for (int jt = 0; jt < 2; ++jt)
                    #pragma unroll
                    for (int q = 0; q < 4; ++q) accj[jt][q] = 0.f;
                #pragma unroll
                for (int kk = 0; kk < 4; ++kk) {
                    uint4 aj = Ah[((v * 4 + kk) * 16 + mt) * 32 + lane];
                    #pragma unroll
                    for (int jt = 0; jt < 2; ++jt) {
                        uint2 bj = *(const uint2*)&s_Bj[((jt * 4 + kk) * 32 + lane) * 2];
                        mma_bf16(accj[jt], (const uint32_t*)&aj, (const uint32_t*)&bj);
                    }
                }
                int m = wid * 16 + (lane >> 2);
                #pragma unroll
                for (int jt = 0; jt < 2; ++jt) {
                    int n = 48 + jt * 8 + (lane & 3) * 2;
                    s_D[n * 128 + m]           = accj[jt][0];
                    s_D[(n + 1) * 128 + m]     = accj[jt][1];
                    s_D[n * 128 + m + 8]       = accj[jt][2];
                    s_D[(n + 1) * 128 + m + 8] = accj[jt][3];
                }
            }
            // gate transpose store (always)
            int m = wid * 16 + (lane >> 2);
            #pragma unroll
            for (int gj = 0; gj < 6; ++gj) {
                int n = (gj >> 1) * 16 + (gj & 1) * 8 + (lane & 3) * 2;
                s_D[n * 128 + m]           = acc[gj][0];
                s_D[(n + 1) * 128 + m]     = acc[gj][1];
                s_D[n * 128 + m + 8]       = acc[gj][2];
                s_D[(n + 1) * 128 + m + 8] = acc[gj][3];
            }
        }
        __syncthreads();

        // ========== epilogue (thread = batch bg, units g0+uh*8 .. +7) ==========
        {
            float xvo = g_xT[t][v][bg];
            float hval[8];
            float* ho = &g_hsT[t][0][0];
            #pragma unroll
            for (int ul = 0; ul < 8; ++ul) {
                int r = uh * 8 + ul;
                float zi = s_bg[r]      + s_D[r * 128 + bl];
                float zf = s_bg[16 + r] + s_D[(16 + r) * 128 + bl];
                float zo = s_bg[32 + r] + s_D[(32 + r) * 128 + bl];
                float jz = s_bj[r] + xvo * s_uu[r];
                if (t > 0) jz += s_D[(48 + r) * 128 + bl];
                float iv = fsigmoid(zi);
                float fv = fsigmoid(zf);
                float ov = fsigmoid(zo);
                float jv = ftanh(jz);
                float cn = cc[ul] * fv + iv * jv;
                cc[ul] = cn;
                hval[ul] = ov * ftanh(cn);
                ho[(size_t)(g0 + r) * TB + bg] = hval[ul];
            }
            #pragma unroll
            for (int p = 0; p < 4; ++p) {
                size_t idx = ((size_t)(ng * 16 + mt_e) * 32 + lane_e + p) * 4 + reg_e;
                g_hA_hi[idx] = pack_bf(hval[2 * p], hval[2 * p + 1]);
            }
        }

        // single grid barrier per step
        __syncthreads();
        if (tid == 0) {
            __threadfence(); atomicAdd(&g_bar, 1u);
            unsigned target = (unsigned)(t + 1) * NCTA;
            while (*((volatile unsigned*)&g_bar) < target) { }
            __threadfence();
        }
        __syncthreads();
    }
}

__global__ void k_alphaA(const float* __restrict__ Fa, const float* __restrict__ Fab) {
    __shared__ float fa[TN]; __shared__ float fabv;
    int v = blockIdx.x, t0 = blockIdx.y * 8, b = threadIdx.x;
    if (threadIdx.x < TN) fa[threadIdx.x] = Fa[v * TN + threadIdx.x];
    if (threadIdx.x == 0) fabv = Fab[v];
    __syncthreads();
    for (int t = t0; t < t0 + 8; ++t) {
        const float* hr = &g_hsT[t][v * TN][0];
        float ap = fabv;
        #pragma unroll 8
        for (int n = 0; n < TN; ++n) ap += hr[n * TB + b] * fa[n];
        g_aunT[t][v][b] = expf(tanhf(ap));
    }
}

__global__ void k_alphaInv() {
    int v = blockIdx.x, b = threadIdx.x;
    float s = 0.f;
    for (int t = 0; t < TT; ++t) s += g_aunT[t][v][b];
    g_inv[v][b] = 1.f / s;
}

__global__ void k_gn() {
    int v = blockIdx.x, nc = blockIdx.y * 2, b = threadIdx.x;
    float a0 = 0.f, a1 = 0.f;
    for (int t = 0; t < TT; ++t) {
        float au = g_aunT[t][v][b];
        const float* hr = &g_hsT[t][v * TN + nc][0];
        a0 += au * hr[0 * TB + b];
        a1 += au * hr[1 * TB + b];
    }
    float inv = g_inv[v][b];
    g_gT[v * TN + nc + 0][b] = a0 * inv;
    g_gT[v * TN + nc + 1][b] = a1 * inv;
}

__global__ void k_alphaOut(float* __restrict__ out) {
    int t = blockIdx.x, b = threadIdx.x;
    float* ao = out + TB;
    #pragma unroll
    for (int v = 0; v < TV; ++v)
        ao[((size_t)b * TT + t) * TV + v] = g_aunT[t][v][b] * g_inv[v][b];
}

__global__ void k_final(const float* __restrict__ Fbw, const float* __restrict__ Fbb,
                        const float* __restrict__ Phw, const float* __restrict__ Phb,
                        float* __restrict__ out) {
    __shared__ float phi[2 * TN], fbw[2 * TN];
    __shared__ float phib, fbb;
    int b = threadIdx.x;
    if (threadIdx.x < 2 * TN) { phi[threadIdx.x] = Phw[threadIdx.x]; fbw[threadIdx.x] = Fbw[threadIdx.x]; }
    if (threadIdx.x == 0) { phib = Phb[0]; fbb = Fbb[0]; }
    __syncthreads();
    float mu[TV], bu[TV], bs = 0.f;
    #pragma unroll
    for (int v = 0; v < TV; ++v) {
        const float* gr = &g_gT[v * TN][0];
        const float* hr = &g_hsT[TT - 1][v * TN][0];
        float m_ = phib, p_ = fbb;
        #pragma unroll 8
        for (int n = 0; n < TN; ++n) {
            float gv = gr[n * TB + b], hv = hr[n * TB + b];
            m_ += gv * phi[n] + hv * phi[TN + n];
            p_ += gv * fbw[n] + hv * fbw[TN + n];
        }
        mu[v] = m_;
        float e = expf(tanhf(p_));
        bu[v] = e; bs += e;
    }
    float ib = 1.f / bs, mean = 0.f;
    float* bout = out + TB + (size_t)TB * TT * TV;
    #pragma unroll
    for (int v = 0; v < TV; ++v) {
        float be = bu[v] * ib;
        mean += be * mu[v];
        bout[(size_t)b * TV + v] = be;
    }
    out[b] = mean;
}

extern "C" void kernel_launch(void* const* d_in, const int* in_sizes, int n_in,
                              void* d_out, int out_size) {
    const float* x    = (const float*)d_in[0];
    const float* U_j  = (const float*)d_in[1];
    const float* W_j  = (const float*)d_in[2];
    const float* b_j  = (const float*)d_in[3];
    const float* Wi   = (const float*)d_in[4];
    const float* bi   = (const float*)d_in[5];
    const float* Wf   = (const float*)d_in[6];
    const float* bf   = (const float*)d_in[7];
    const float* Wo   = (const float*)d_in[8];
    const float* bo   = (const float*)d_in[9];
    const float* Fa   = (const float*)d_in[10];
    const float* Fab  = (const float*)d_in[11];
    const float* Fbw  = (const float*)d_in[12];
    const float* Fbb  = (const float*)d_in[13];
    const float* Phw  = (const float*)d_in[14];
    const float* Phb  = (const float*)d_in[15];
    float* out = (float*)d_out;

    static const int SMEM = 24960 * 4 + 512 * 4 + 64 * 128 * 4;  // 134656 B
    cudaFuncSetAttribute(k_recur, cudaFuncAttributeMaxDynamicSharedMemorySize, SMEM);

    k_xT<<<TT * TV, TB>>>(x);
    k_xfrag<<<TT, 256>>>(x);
    k_wfrag<<<dim3(384, 65), 64>>>(Wi, Wf, Wo);
    k_recur<<<NCTA, RTHREADS, SMEM>>>(U_j, W_j, b_j, bi, bf, bo);
    k_alphaA<<<dim3(TV, 25), TB>>>(Fa, Fab);
    k_alphaInv<<<TV, TB>>>();
    k_gn<<<dim3(TV, 32), TB>>>();
    k_alphaOut<<<TT, TB>>>(out);
    k_final<<<1, TB>>>(Fbw, Fbb, Phw, Phb, out);
}